// round 8
// baseline (speedup 1.0000x reference)
#include <cuda_runtime.h>
#include <cuda_bf16.h>
#include <math.h>

#define NN  50000
#define EE  800000
#define INC 512
#define HH  64
#define OC  40
#define NL  64
#define NBLK ((NN + 1023) / 1024)       // 49 scan blocks
#define EEP (EE + 7 * NN + 16)          // padded CSR capacity + prefetch slack
#define NBUN (NN / 4)                   // 12500 bundles
#define ZIDX(k) ((k) + ((k) >> 3))      // smem anti-conflict index (max 71)

typedef unsigned long long ull;

__device__ __forceinline__ ull fma2(ull a, ull b, ull c) {
    ull d; asm("fma.rn.f32x2 %0, %1, %2, %3;" : "=l"(d) : "l"(a), "l"(b), "l"(c)); return d;
}
__device__ __forceinline__ ull add2(ull a, ull b) {
    ull d; asm("add.rn.f32x2 %0, %1, %2;" : "=l"(d) : "l"(a), "l"(b)); return d;
}
__device__ __forceinline__ ull mul2(ull a, ull b) {
    ull d; asm("mul.rn.f32x2 %0, %1, %2;" : "=l"(d) : "l"(a), "l"(b)); return d;
}
__device__ __forceinline__ ull pack2(float lo, float hi) {
    ull d; asm("mov.b64 %0, {%1, %2};" : "=l"(d) : "f"(lo), "f"(hi)); return d;
}
__device__ __forceinline__ float2 unpk(ull v) {
    float lo, hi; asm("mov.b64 {%0, %1}, %2;" : "=f"(lo), "=f"(hi) : "l"(v));
    return make_float2(lo, hi);
}

// ---------------- device scratch ----------------
__device__ float g_dinv[NN];
__device__ int   g_cnt[NN];
__device__ int   g_rowptr[NN + 1];
__device__ int   g_bsum[NBLK];
__device__ int   g_flag[64];
__device__ int   g_fill[NN];
__device__ int2  g_edge[EEP];           // (col, val-bits), node lists padded to 8
__device__ float g_x0[NN * HH];
__device__ float g_hbuf[2][NN * HH];
__device__ int   g_is64;

// ---------------- launch 0: lin1 (+ zero counts + int64 detect) ----------------
__global__ __launch_bounds__(256) void k_lin1(const float* __restrict__ x,
                                              const float* __restrict__ w1,
                                              const float* __restrict__ b1,
                                              const int* __restrict__ ei32) {
    int gtid = blockIdx.x * 256 + threadIdx.x;
    if (gtid < NN) g_cnt[gtid] = 0;
    if (gtid == 0) {
        int all0 = 1;
        for (int j = 0; j < 64; j++)
            if (ei32[2 * j + 1] != 0) all0 = 0;
        g_is64 = all0;
    }

    __shared__ float xsT[32][129];
    __shared__ float ws[32 * 64];
    int t = threadIdx.x;
    int half = t >> 7;
    int nl = t & 127;
    int node0 = blockIdx.x * 128;

    ull acc2[16];
#pragma unroll
    for (int c = 0; c < 16; c++) acc2[c] = 0ull;

    for (int kt = 0; kt < INC; kt += 32) {
        for (int i = t; i < 32 * 64; i += 256)
            ws[i] = w1[(kt + (i >> 6)) * 64 + (i & 63)];
        for (int i = t; i < 1024; i += 256) {
            int r = i >> 3, c4 = i & 7;
            int node = node0 + r;
            float4 v = make_float4(0.f, 0.f, 0.f, 0.f);
            if (node < NN)
                v = *(const float4*)&x[(size_t)node * INC + kt + c4 * 4];
            xsT[c4 * 4 + 0][r] = v.x;
            xsT[c4 * 4 + 1][r] = v.y;
            xsT[c4 * 4 + 2][r] = v.z;
            xsT[c4 * 4 + 3][r] = v.w;
        }
        __syncthreads();
#pragma unroll 4
        for (int k = 0; k < 32; k++) {
            float xv = xsT[k][nl];
            ull xv2 = pack2(xv, xv);
            const ulonglong2* wr = (const ulonglong2*)&ws[k * 64 + half * 32];
#pragma unroll
            for (int c = 0; c < 8; c++) {
                ulonglong2 wp = wr[c];
                acc2[2 * c + 0] = fma2(xv2, wp.x, acc2[2 * c + 0]);
                acc2[2 * c + 1] = fma2(xv2, wp.y, acc2[2 * c + 1]);
            }
        }
        __syncthreads();
    }
    int node = node0 + nl;
    if (node < NN) {
        float* px = &g_x0[node * 64 + half * 32];
        float* ph = &g_hbuf[0][node * 64 + half * 32];
#pragma unroll
        for (int c4 = 0; c4 < 8; c4++) {
            float2 sa = unpk(acc2[2 * c4]);
            float2 sb = unpk(acc2[2 * c4 + 1]);
            float4 v;
            v.x = fmaxf(sa.x + b1[half * 32 + c4 * 4 + 0], 0.f);
            v.y = fmaxf(sa.y + b1[half * 32 + c4 * 4 + 1], 0.f);
            v.z = fmaxf(sb.x + b1[half * 32 + c4 * 4 + 2], 0.f);
            v.w = fmaxf(sb.y + b1[half * 32 + c4 * 4 + 3], 0.f);
            *(float4*)&px[c4 * 4] = v;
            *(float4*)&ph[c4 * 4] = v;
        }
    }
}

// ---------------- launch 1: count ----------------
__global__ void k_count(const void* eiv) {
    int e = blockIdx.x * blockDim.x + threadIdx.x;
    if (e < 64) g_flag[e] = 0;
    if (e < 16) g_edge[EEP - 16 + e] = make_int2(0, 0);  // prefetch slack
    if (e >= EE) return;
    int d;
    if (g_is64) d = (int)((const long long*)eiv)[EE + e];
    else        d = ((const int*)eiv)[EE + e];
    atomicAdd(&g_cnt[d], 1);
}

// ---------------- launch 2: single-pass scan over PADDED counts ----------------
__global__ __launch_bounds__(1024) void k_scan() {
    __shared__ int wsum[32];
    __shared__ int pred[64];
    int t = threadIdx.x, b = blockIdx.x;
    int i = b * 1024 + t;
    int c = (i < NN) ? g_cnt[i] : 0;
    int v = (c + 7) & ~7;               // padded degree
    int lane = t & 31, wid = t >> 5;
    int s = v;
#pragma unroll
    for (int o = 1; o < 32; o <<= 1) {
        int u = __shfl_up_sync(0xffffffffu, s, o);
        if (lane >= o) s += u;
    }
    if (lane == 31) wsum[wid] = s;
    __syncthreads();
    if (wid == 0) {
        int ws = wsum[lane];
#pragma unroll
        for (int o = 1; o < 32; o <<= 1) {
            int u = __shfl_up_sync(0xffffffffu, ws, o);
            if (lane >= o) ws += u;
        }
        wsum[lane] = ws;
    }
    __syncthreads();
    int excl = s - v + (wid > 0 ? wsum[wid - 1] : 0);
    if (t == 1023) {
        g_bsum[b] = excl + v;
        __threadfence();
        atomicExch(&g_flag[b], 1);
    }
    if (t < 64) {
        int pv = 0;
        if (t < b) {
            while (atomicAdd(&g_flag[t], 0) == 0) {}
            pv = g_bsum[t];
        }
        pred[t] = pv;
    }
    __syncthreads();
    for (int o = 32; o > 0; o >>= 1) {
        if (t < o) pred[t] += pred[t + o];
        __syncthreads();
    }
    int off = pred[0];
    if (i < NN) {
        int rp = excl + off;
        g_rowptr[i] = rp;
        g_dinv[i] = rsqrtf((float)(c + 1));
        g_fill[i] = 0;
        for (int j = c; j < v; j++)
            g_edge[rp + j] = make_int2(0, 0);
        if (i == NN - 1) g_rowptr[NN] = rp + v;
    }
}

// ---------------- launch 3: fill CSR ----------------
__global__ void k_fill(const void* eiv) {
    int e = blockIdx.x * blockDim.x + threadIdx.x;
    if (e >= EE) return;
    int s, d;
    if (g_is64) {
        const long long* ei = (const long long*)eiv;
        s = (int)ei[e];
        d = (int)ei[EE + e];
    } else {
        const int* ei = (const int*)eiv;
        s = ei[e];
        d = ei[EE + e];
    }
    int pos = g_rowptr[d] + atomicAdd(&g_fill[d], 1);
    g_edge[pos] = make_int2(s, __float_as_int(g_dinv[s] * g_dinv[d]));
}

// ---------------- layer: warp = exactly ONE 4-node bundle ----------------
// Gather: broadcast edge loads, f32x2 FMA; GEMM: duplicated-z staging + FFMA2.
__global__ __launch_bounds__(256) void k_layer(const float* __restrict__ W,
                                               float beta, int p) {
    __shared__ float ws[64 * 64];
    __shared__ float4 zAB[8][72];       // {zA,zA,zB,zB} per k (anti-conflict pad)
    __shared__ float4 zCD[8][72];       // {zC,zC,zD,zD}
    int t = threadIdx.x, w = t >> 5, lane = t & 31;
    int l2 = lane * 2;
    int hl = lane >> 4;                 // edge parity within pair
    int fl = lane & 15;                 // feature quad id
    for (int i = t; i < 4096; i += 256) ws[i] = W[i];
    __syncthreads();

    int base = (blockIdx.x * 8 + w) * 4;
    if (base >= NN) return;

    const ulonglong2* __restrict__ hin2 = (const ulonglong2*)g_hbuf[p];
    const ulonglong2* __restrict__ x02p = (const ulonglong2*)g_x0;
    float* __restrict__ hout = g_hbuf[p ^ 1];
    float ob = 1.f - beta;
    ull h05 = pack2(0.5f, 0.5f);

    int rp = 0;
    if (lane < 5) rp = g_rowptr[base + lane];

    float zf[4][4];                     // [q][component within quad]
#pragma unroll
    for (int q = 0; q < 4; q++) {
        int node = base + q;
        int e0 = __shfl_sync(0xffffffffu, rp, q);
        int e1 = __shfl_sync(0xffffffffu, rp, q + 1);
        int pd = e1 - e0;               // multiple of 8
        ull a01 = 0, a23 = 0, b01 = 0, b23 = 0;
        ull c01 = 0, c23 = 0, d01 = 0, d23 = 0;
        if (pd > 0) {
            const int2* ep = g_edge + e0;
            int2 eA = ep[hl], eB = ep[2 + hl], eC = ep[4 + hl], eD = ep[6 + hl];
            for (int j = 8;; j += 8) {
                int2 nA = ep[j + hl];
                int2 nB = ep[j + 2 + hl];
                int2 nC = ep[j + 4 + hl];
                int2 nD = ep[j + 6 + hl];
                ulonglong2 hA = hin2[eA.x * 16 + fl];
                ulonglong2 hB = hin2[eB.x * 16 + fl];
                ulonglong2 hC = hin2[eC.x * 16 + fl];
                ulonglong2 hD = hin2[eD.x * 16 + fl];
                float vA = __int_as_float(eA.y);
                float vB = __int_as_float(eB.y);
                float vC = __int_as_float(eC.y);
                float vD = __int_as_float(eD.y);
                ull pA = pack2(vA, vA), pB = pack2(vB, vB);
                ull pC = pack2(vC, vC), pD = pack2(vD, vD);
                a01 = fma2(pA, hA.x, a01); a23 = fma2(pA, hA.y, a23);
                b01 = fma2(pB, hB.x, b01); b23 = fma2(pB, hB.y, b23);
                c01 = fma2(pC, hC.x, c01); c23 = fma2(pC, hC.y, c23);
                d01 = fma2(pD, hD.x, d01); d23 = fma2(pD, hD.y, d23);
                if (j >= pd) break;
                eA = nA; eB = nB; eC = nC; eD = nD;
            }
        }
        a01 = add2(add2(a01, b01), add2(c01, d01));
        a23 = add2(add2(a23, b23), add2(c23, d23));
        a01 = add2(a01, __shfl_xor_sync(0xffffffffu, a01, 16));
        a23 = add2(a23, __shfl_xor_sync(0xffffffffu, a23, 16));
        if (hl == 0) {
            float di = g_dinv[node];
            ull dd2 = pack2(di * di, di * di);
            ulonglong2 hm = hin2[node * 16 + fl];
            ulonglong2 xm = x02p[node * 16 + fl];
            ull z01 = mul2(h05, add2(fma2(dd2, hm.x, a01), xm.x));
            ull z23 = mul2(h05, add2(fma2(dd2, hm.y, a23), xm.y));
            float2 u0 = unpk(z01), u1 = unpk(z23);
            zf[q][0] = u0.x; zf[q][1] = u0.y; zf[q][2] = u1.x; zf[q][3] = u1.y;
        }
    }
    // stage duplicated z: zAB[k] = {zA,zA,zB,zB}, zCD[k] = {zC,zC,zD,zD}
    if (hl == 0) {
#pragma unroll
        for (int j = 0; j < 4; j++) {
            int k = fl * 4 + j;
            zAB[w][ZIDX(k)] = make_float4(zf[0][j], zf[0][j], zf[1][j], zf[1][j]);
            zCD[w][ZIDX(k)] = make_float4(zf[2][j], zf[2][j], zf[3][j], zf[3][j]);
        }
    }
    __syncwarp();

    ull accA = 0, accB = 0, accC = 0, accD = 0;   // {col l2, col l2+1} per node
#pragma unroll
    for (int k = 0; k < 64; k++) {
        ulonglong2 ab = *(const ulonglong2*)&zAB[w][ZIDX(k)];
        ulonglong2 cd = *(const ulonglong2*)&zCD[w][ZIDX(k)];
        ull wk2 = *(const ull*)&ws[k * 64 + l2];
        accA = fma2(ab.x, wk2, accA);
        accB = fma2(ab.y, wk2, accB);
        accC = fma2(cd.x, wk2, accC);
        accD = fma2(cd.y, wk2, accD);
    }
    float4 uA0 = zAB[w][ZIDX(l2)], uA1 = zAB[w][ZIDX(l2 + 1)];
    float4 uC0 = zCD[w][ZIDX(l2)], uC1 = zCD[w][ZIDX(l2 + 1)];
    float2 sA = unpk(accA), sB = unpk(accB), sC = unpk(accC), sD = unpk(accD);
    *(float2*)&hout[(base + 0) * 64 + l2] =
        make_float2(fmaxf(ob * uA0.x + beta * sA.x, 0.f),
                    fmaxf(ob * uA1.x + beta * sA.y, 0.f));
    *(float2*)&hout[(base + 1) * 64 + l2] =
        make_float2(fmaxf(ob * uA0.z + beta * sB.x, 0.f),
                    fmaxf(ob * uA1.z + beta * sB.y, 0.f));
    *(float2*)&hout[(base + 2) * 64 + l2] =
        make_float2(fmaxf(ob * uC0.x + beta * sC.x, 0.f),
                    fmaxf(ob * uC1.x + beta * sC.y, 0.f));
    *(float2*)&hout[(base + 3) * 64 + l2] =
        make_float2(fmaxf(ob * uC0.z + beta * sD.x, 0.f),
                    fmaxf(ob * uC1.z + beta * sD.y, 0.f));
}

// ---------------- output: lin2 + log_softmax ----------------
__global__ __launch_bounds__(256) void k_out(const float* __restrict__ w2,
                                             const float* __restrict__ b2,
                                             float* __restrict__ out) {
    __shared__ float ws[64 * OC];
    __shared__ float bs[OC];
    __shared__ float zsm[8][64];
    int t = threadIdx.x, w = t >> 5, lane = t & 31;
    for (int i = t; i < 64 * OC; i += 256) ws[i] = w2[i];
    if (t < OC) bs[t] = b2[t];
    __syncthreads();

    const float* h = g_hbuf[0];  // NL even -> final state in buffer 0
    int warpG = blockIdx.x * 8 + w;
    int nW = gridDim.x * 8;

    for (int node = warpG; node < NN; node += nW) {
        float2 h2 = *(const float2*)&h[node * 64 + lane * 2];
        *(float2*)&zsm[w][lane * 2] = h2;
        __syncwarp();
        int c0 = lane;
        int c1 = lane + 32;
        float v0 = bs[c0];
        float v1 = (lane < 8) ? bs[c1] : 0.f;
#pragma unroll
        for (int k = 0; k < 64; k++) {
            float zk = zsm[w][k];
            v0 += zk * ws[k * OC + c0];
            if (lane < 8) v1 += zk * ws[k * OC + c1];
        }
        float m = v0;
        if (lane < 8) m = fmaxf(m, v1);
#pragma unroll
        for (int o = 16; o > 0; o >>= 1)
            m = fmaxf(m, __shfl_xor_sync(0xffffffffu, m, o));
        float se = expf(v0 - m) + ((lane < 8) ? expf(v1 - m) : 0.f);
#pragma unroll
        for (int o = 16; o > 0; o >>= 1)
            se += __shfl_xor_sync(0xffffffffu, se, o);
        float lse = m + logf(se);
        out[node * OC + c0] = v0 - lse;
        if (lane < 8) out[node * OC + c1] = v1 - lse;
        __syncwarp();
    }
}

// ---------------- launch ----------------
extern "C" void kernel_launch(void* const* d_in, const int* in_sizes, int n_in,
                              void* d_out, int out_size) {
    (void)in_sizes; (void)n_in; (void)out_size;
    const float* x  = (const float*)d_in[0];
    const void*  ei = d_in[1];
    const float* w1 = (const float*)d_in[2];
    const float* b1 = (const float*)d_in[3];
    const float* cw = (const float*)d_in[4];
    const float* w2 = (const float*)d_in[5];
    const float* b2 = (const float*)d_in[6];
    float* out = (float*)d_out;

    k_lin1<<<(NN + 127) / 128, 256>>>(x, w1, b1, (const int*)ei);
    k_count<<<(EE + 255) / 256, 256>>>(ei);
    k_scan<<<NBLK, 1024>>>();
    k_fill<<<(EE + 255) / 256, 256>>>(ei);

    int lgrid = (NBUN + 7) / 8;   // 1563 blocks, one bundle per warp
    for (int l = 0; l < NL; l++) {
        float beta = logf(1.0f / (float)(l + 1) + 1.0f);
        k_layer<<<lgrid, 256>>>(cw + (size_t)l * HH * HH, beta, l & 1);
    }
    k_out<<<512, 256>>>(w2, b2, out);
}

// round 9
// speedup vs baseline: 1.2402x; 1.2402x over previous
#include <cuda_runtime.h>
#include <cuda_bf16.h>
#include <math.h>

#define NN  50000
#define EE  800000
#define INC 512
#define HH  64
#define OC  40
#define NL  64
#define NBLK ((NN + 1023) / 1024)   // 49 scan blocks
#define CSTRIDE (391 * 256)         // lin1 grid stride for edge counting

// ---------------- device scratch (all zero-init; replay-invariant) ----------------
__device__ float g_dinv[NN];
__device__ int   g_cnt[NN];          // zeroed by k_scan after use
__device__ int   g_rowptr[NN + 1];
__device__ int   g_bsumbuf[2][NBLK]; // lookback aggregates, parity-buffered
__device__ int   g_done;             // finished-block counter for k_scan
__device__ int   g_par;              // parity, flipped each k_scan execution
__device__ int   g_fill[NN];         // zeroed by k_scan
__device__ int   g_col[EE];
__device__ float g_val[EE];
__device__ float g_x0[NN * HH];
__device__ float g_hbuf[2][NN * HH];
__device__ int   g_is64;

// ---------------- launch 0: lin1 + edge degree count + dtype detect ----------------
__global__ __launch_bounds__(256) void k_lin1(const float* __restrict__ x,
                                              const float* __restrict__ w1,
                                              const float* __restrict__ b1,
                                              const void* __restrict__ eiv) {
    // --- edge counting (overlaps with the GEMM below; g_cnt pre-zeroed) ---
    {
        const int* ei32 = (const int*)eiv;
        // per-thread dtype probe: int64 values < 2^31 have zero odd words
        bool is64 = (ei32[1] == 0) & (ei32[3] == 0) & (ei32[5] == 0) & (ei32[7] == 0);
        int gtid = blockIdx.x * 256 + threadIdx.x;
        if (gtid == 0) g_is64 = is64 ? 1 : 0;
        if (is64) {
            const long long* ei = (const long long*)eiv;
            for (int e = gtid; e < EE; e += CSTRIDE)
                atomicAdd(&g_cnt[(int)ei[EE + e]], 1);
        } else {
            for (int e = gtid; e < EE; e += CSTRIDE)
                atomicAdd(&g_cnt[ei32[EE + e]], 1);
        }
    }

    __shared__ float xsT[32][129];
    __shared__ float ws[32 * 64];
    int t = threadIdx.x;
    int half = t >> 7;
    int nl = t & 127;
    int node0 = blockIdx.x * 128;

    float acc[32];
#pragma unroll
    for (int c = 0; c < 32; c++) acc[c] = 0.f;

    for (int kt = 0; kt < INC; kt += 32) {
        for (int i = t; i < 32 * 64; i += 256)
            ws[i] = w1[(kt + (i >> 6)) * 64 + (i & 63)];
        for (int i = t; i < 1024; i += 256) {
            int r = i >> 3, c4 = i & 7;
            int node = node0 + r;
            float4 v = make_float4(0.f, 0.f, 0.f, 0.f);
            if (node < NN)
                v = *(const float4*)&x[(size_t)node * INC + kt + c4 * 4];
            xsT[c4 * 4 + 0][r] = v.x;
            xsT[c4 * 4 + 1][r] = v.y;
            xsT[c4 * 4 + 2][r] = v.z;
            xsT[c4 * 4 + 3][r] = v.w;
        }
        __syncthreads();
#pragma unroll 4
        for (int k = 0; k < 32; k++) {
            float xv = xsT[k][nl];
            const float4* wr = (const float4*)&ws[k * 64 + half * 32];
#pragma unroll
            for (int c4 = 0; c4 < 8; c4++) {
                float4 w4 = wr[c4];
                acc[c4 * 4 + 0] += xv * w4.x;
                acc[c4 * 4 + 1] += xv * w4.y;
                acc[c4 * 4 + 2] += xv * w4.z;
                acc[c4 * 4 + 3] += xv * w4.w;
            }
        }
        __syncthreads();
    }
    int node = node0 + nl;
    if (node < NN) {
        float* px = &g_x0[node * 64 + half * 32];
        float* ph = &g_hbuf[0][node * 64 + half * 32];
#pragma unroll
        for (int c4 = 0; c4 < 8; c4++) {
            float4 v;
            v.x = fmaxf(acc[c4 * 4 + 0] + b1[half * 32 + c4 * 4 + 0], 0.f);
            v.y = fmaxf(acc[c4 * 4 + 1] + b1[half * 32 + c4 * 4 + 1], 0.f);
            v.z = fmaxf(acc[c4 * 4 + 2] + b1[half * 32 + c4 * 4 + 2], 0.f);
            v.w = fmaxf(acc[c4 * 4 + 3] + b1[half * 32 + c4 * 4 + 3], 0.f);
            *(float4*)&px[c4 * 4] = v;
            *(float4*)&ph[c4 * 4] = v;
        }
    }
}

// ---------------- launch 1: single-pass lookback scan (replay-safe) ----------------
__global__ __launch_bounds__(1024) void k_scan() {
    __shared__ int wsum[32];
    __shared__ int pred[64];
    int par = g_par;                    // stable during this launch
    int t = threadIdx.x, b = blockIdx.x;
    int i = b * 1024 + t;
    int v = (i < NN) ? g_cnt[i] : 0;
    int lane = t & 31, wid = t >> 5;
    int s = v;
#pragma unroll
    for (int o = 1; o < 32; o <<= 1) {
        int u = __shfl_up_sync(0xffffffffu, s, o);
        if (lane >= o) s += u;
    }
    if (lane == 31) wsum[wid] = s;
    __syncthreads();
    if (wid == 0) {
        int ws = wsum[lane];
#pragma unroll
        for (int o = 1; o < 32; o <<= 1) {
            int u = __shfl_up_sync(0xffffffffu, ws, o);
            if (lane >= o) ws += u;
        }
        wsum[lane] = ws;
    }
    __syncthreads();
    int excl = s - v + (wid > 0 ? wsum[wid - 1] : 0);
    if (t == 1023)
        atomicExch(&g_bsumbuf[par][b], (excl + v) | (1 << 30));  // publish aggregate
    if (t < 64) {
        int pv = 0;
        if (t < b) {
            while ((pv = atomicAdd(&g_bsumbuf[par][t], 0)) == 0) {}
            pv &= ~(1 << 30);
        }
        pred[t] = pv;
    }
    __syncthreads();
    for (int o = 32; o > 0; o >>= 1) {
        if (t < o) pred[t] += pred[t + o];
        __syncthreads();
    }
    int off = pred[0];
    if (i < NN) {
        g_rowptr[i] = excl + off;
        g_dinv[i] = rsqrtf((float)(v + 1));
        g_fill[i] = 0;
        g_cnt[i] = 0;                    // restore for next replay
    }
    if (i == NN - 1) g_rowptr[NN] = EE;
    // replay-state reset: last block to finish resets this parity's buffer
    __syncthreads();
    __threadfence();
    if (t == 0) {
        int d = atomicAdd(&g_done, 1);
        if (d == NBLK - 1) {
            for (int j = 0; j < NBLK; j++) g_bsumbuf[par][j] = 0;
            g_done = 0;
            __threadfence();
            g_par = par ^ 1;
        }
    }
}

// ---------------- launch 2: fill CSR ----------------
__global__ void k_fill(const void* eiv) {
    int e = blockIdx.x * blockDim.x + threadIdx.x;
    if (e >= EE) return;
    int s, d;
    if (g_is64) {
        const long long* ei = (const long long*)eiv;
        s = (int)ei[e];
        d = (int)ei[EE + e];
    } else {
        const int* ei = (const int*)eiv;
        s = ei[e];
        d = ei[EE + e];
    }
    int pos = g_rowptr[d] + atomicAdd(&g_fill[d], 1);
    g_col[pos] = s;
    g_val[pos] = g_dinv[s] * g_dinv[d];
}

// ---------------- launch 3+: fused GCNII layer (R5 baseline) ----------------
// warp = 4 nodes. Lane owns feature quad ((lane&15)*4); half-warps split edge
// pairs -> LDG.128 per lane, 2 edges/step, 8-edge unroll; shared-W GEMM.
__global__ __launch_bounds__(256) void k_layer(const float* __restrict__ W,
                                               float beta, int p) {
    __shared__ float ws[64 * 64];
    __shared__ float4 zq[8][64];
    int t = threadIdx.x, w = t >> 5, lane = t & 31;
    int l2 = lane * 2;
    int hl = lane >> 4;          // edge parity within pair
    int fl = lane & 15;          // feature quad id
    for (int i = t; i < 4096; i += 256) ws[i] = W[i];
    __syncthreads();

    const float4* __restrict__ hin4 = (const float4*)g_hbuf[p];
    const float4* __restrict__ x04 = (const float4*)g_x0;
    float* __restrict__ hout = g_hbuf[p ^ 1];
    int warpG = blockIdx.x * 8 + w;
    int nW = gridDim.x * 8;
    float ob = 1.f - beta;

    for (int base = warpG * 4; base < NN; base += nW * 4) {
        float4 z4[4];
#pragma unroll
        for (int q = 0; q < 4; q++) {
            int node = base + q;
            if (node >= NN) { z4[q] = make_float4(0.f, 0.f, 0.f, 0.f); continue; }
            float4 acc = make_float4(0.f, 0.f, 0.f, 0.f);
            int e0 = g_rowptr[node], e1 = g_rowptr[node + 1];
            for (int eb = e0; eb < e1; eb += 32) {
                int ee = eb + lane;
                bool okl = ee < e1;
                int cc = okl ? g_col[ee] : 0;
                float vv = okl ? g_val[ee] : 0.f;
                int cn = min(32, e1 - eb);
                for (int j = 0; j < cn; j += 8) {
                    int sA = __shfl_sync(0xffffffffu, cc, j + hl);
                    int sB = __shfl_sync(0xffffffffu, cc, j + 2 + hl);
                    int sC = __shfl_sync(0xffffffffu, cc, j + 4 + hl);
                    int sD = __shfl_sync(0xffffffffu, cc, j + 6 + hl);
                    float vA = __shfl_sync(0xffffffffu, vv, j + hl);
                    float vB = __shfl_sync(0xffffffffu, vv, j + 2 + hl);
                    float vC = __shfl_sync(0xffffffffu, vv, j + 4 + hl);
                    float vD = __shfl_sync(0xffffffffu, vv, j + 6 + hl);
                    float4 hA = hin4[sA * 16 + fl];
                    float4 hB = hin4[sB * 16 + fl];
                    float4 hC = hin4[sC * 16 + fl];
                    float4 hD = hin4[sD * 16 + fl];
                    acc.x += vA * hA.x; acc.y += vA * hA.y;
                    acc.z += vA * hA.z; acc.w += vA * hA.w;
                    acc.x += vB * hB.x; acc.y += vB * hB.y;
                    acc.z += vB * hB.z; acc.w += vB * hB.w;
                    acc.x += vC * hC.x; acc.y += vC * hC.y;
                    acc.z += vC * hC.z; acc.w += vC * hC.w;
                    acc.x += vD * hD.x; acc.y += vD * hD.y;
                    acc.z += vD * hD.z; acc.w += vD * hD.w;
                }
            }
            acc.x += __shfl_xor_sync(0xffffffffu, acc.x, 16);
            acc.y += __shfl_xor_sync(0xffffffffu, acc.y, 16);
            acc.z += __shfl_xor_sync(0xffffffffu, acc.z, 16);
            acc.w += __shfl_xor_sync(0xffffffffu, acc.w, 16);
            if (hl == 0) {
                float di = g_dinv[node];
                float dd = di * di;
                float4 hme = hin4[node * 16 + fl];
                float4 xm = x04[node * 16 + fl];
                z4[q].x = 0.5f * (acc.x + dd * hme.x) + 0.5f * xm.x;
                z4[q].y = 0.5f * (acc.y + dd * hme.y) + 0.5f * xm.y;
                z4[q].z = 0.5f * (acc.z + dd * hme.z) + 0.5f * xm.z;
                z4[q].w = 0.5f * (acc.w + dd * hme.w) + 0.5f * xm.w;
            }
        }
        if (hl == 0) {
            zq[w][fl * 4 + 0] = make_float4(z4[0].x, z4[1].x, z4[2].x, z4[3].x);
            zq[w][fl * 4 + 1] = make_float4(z4[0].y, z4[1].y, z4[2].y, z4[3].y);
            zq[w][fl * 4 + 2] = make_float4(z4[0].z, z4[1].z, z4[2].z, z4[3].z);
            zq[w][fl * 4 + 3] = make_float4(z4[0].w, z4[1].w, z4[2].w, z4[3].w);
        }
        __syncwarp();

        float4 s0 = make_float4(0.f, 0.f, 0.f, 0.f);
        float4 s1 = make_float4(0.f, 0.f, 0.f, 0.f);
#pragma unroll
        for (int k = 0; k < 64; k++) {
            float4 zk = zq[w][k];
            float2 wk = *(const float2*)&ws[k * 64 + l2];
            s0.x += zk.x * wk.x; s0.y += zk.y * wk.x;
            s0.z += zk.z * wk.x; s0.w += zk.w * wk.x;
            s1.x += zk.x * wk.y; s1.y += zk.y * wk.y;
            s1.z += zk.z * wk.y; s1.w += zk.w * wk.y;
        }
        float4 zc0 = zq[w][l2];
        float4 zc1 = zq[w][l2 + 1];
        float zr0[4] = {zc0.x, zc0.y, zc0.z, zc0.w};
        float zr1[4] = {zc1.x, zc1.y, zc1.z, zc1.w};
        float sc0[4] = {s0.x, s0.y, s0.z, s0.w};
        float sc1[4] = {s1.x, s1.y, s1.z, s1.w};
#pragma unroll
        for (int q = 0; q < 4; q++) {
            int node = base + q;
            if (node < NN) {
                float o0 = fmaxf(ob * zr0[q] + beta * sc0[q], 0.f);
                float o1 = fmaxf(ob * zr1[q] + beta * sc1[q], 0.f);
                *(float2*)&hout[node * 64 + l2] = make_float2(o0, o1);
            }
        }
        __syncwarp();
    }
}

// ---------------- output: lin2 + log_softmax ----------------
__global__ __launch_bounds__(256) void k_out(const float* __restrict__ w2,
                                             const float* __restrict__ b2,
                                             float* __restrict__ out) {
    __shared__ float ws[64 * OC];
    __shared__ float bs[OC];
    __shared__ float zsm[8][64];
    int t = threadIdx.x, w = t >> 5, lane = t & 31;
    for (int i = t; i < 64 * OC; i += 256) ws[i] = w2[i];
    if (t < OC) bs[t] = b2[t];
    __syncthreads();

    const float* h = g_hbuf[0];  // NL even -> final state in buffer 0
    int warpG = blockIdx.x * 8 + w;
    int nW = gridDim.x * 8;

    for (int node = warpG; node < NN; node += nW) {
        float2 h2 = *(const float2*)&h[node * 64 + lane * 2];
        *(float2*)&zsm[w][lane * 2] = h2;
        __syncwarp();
        int c0 = lane;
        int c1 = lane + 32;
        float v0 = bs[c0];
        float v1 = (lane < 8) ? bs[c1] : 0.f;
#pragma unroll
        for (int k = 0; k < 64; k++) {
            float zk = zsm[w][k];
            v0 += zk * ws[k * OC + c0];
            if (lane < 8) v1 += zk * ws[k * OC + c1];
        }
        float m = v0;
        if (lane < 8) m = fmaxf(m, v1);
#pragma unroll
        for (int o = 16; o > 0; o >>= 1)
            m = fmaxf(m, __shfl_xor_sync(0xffffffffu, m, o));
        float se = expf(v0 - m) + ((lane < 8) ? expf(v1 - m) : 0.f);
#pragma unroll
        for (int o = 16; o > 0; o >>= 1)
            se += __shfl_xor_sync(0xffffffffu, se, o);
        float lse = m + logf(se);
        out[node * OC + c0] = v0 - lse;
        if (lane < 8) out[node * OC + c1] = v1 - lse;
        __syncwarp();
    }
}

// ---------------- launch ----------------
extern "C" void kernel_launch(void* const* d_in, const int* in_sizes, int n_in,
                              void* d_out, int out_size) {
    (void)in_sizes; (void)n_in; (void)out_size;
    const float* x  = (const float*)d_in[0];
    const void*  ei = d_in[1];
    const float* w1 = (const float*)d_in[2];
    const float* b1 = (const float*)d_in[3];
    const float* cw = (const float*)d_in[4];
    const float* w2 = (const float*)d_in[5];
    const float* b2 = (const float*)d_in[6];
    float* out = (float*)d_out;

    k_lin1<<<391, 256>>>(x, w1, b1, ei);        // #0: lin1 + count + detect
    k_scan<<<NBLK, 1024>>>();                    // #1
    k_fill<<<(EE + 255) / 256, 256>>>(ei);       // #2
    for (int l = 0; l < NL; l++) {               // #3 = layer 0 (profiled)
        float beta = logf(1.0f / (float)(l + 1) + 1.0f);
        k_layer<<<148 * 8, 256>>>(cw + (size_t)l * HH * HH, beta, l & 1);
    }
    k_out<<<512, 256>>>(w2, b2, out);
}

// round 10
// speedup vs baseline: 1.2635x; 1.0188x over previous
#include <cuda_runtime.h>
#include <cuda_bf16.h>
#include <math.h>

#define NN  50000
#define EE  800000
#define INC 512
#define HH  64
#define OC  40
#define NL  64
#define NBLK ((NN + 1023) / 1024)   // 49 scan blocks
#define CSTRIDE (391 * 256)         // lin1 grid stride for edge counting

// ---------------- device scratch (all zero-init; replay-invariant) ----------------
__device__ float g_dinv[NN];
__device__ int   g_cnt[NN];          // zeroed by k_scan after use
__device__ int   g_rowptr[NN + 1];
__device__ int   g_bsumbuf[2][NBLK]; // lookback aggregates, parity-buffered
__device__ int   g_done;
__device__ int   g_par;
__device__ int   g_fill[NN];
__device__ int2  g_edge[EE];         // (col, val-bits)
__device__ float g_x0[NN * HH];
__device__ float g_hbuf[2][NN * HH];
__device__ int   g_is64;

// ---------------- launch 0: lin1 + edge degree count + dtype detect ----------------
__global__ __launch_bounds__(256) void k_lin1(const float* __restrict__ x,
                                              const float* __restrict__ w1,
                                              const float* __restrict__ b1,
                                              const void* __restrict__ eiv) {
    {
        const int* ei32 = (const int*)eiv;
        bool is64 = (ei32[1] == 0) & (ei32[3] == 0) & (ei32[5] == 0) & (ei32[7] == 0);
        int gtid = blockIdx.x * 256 + threadIdx.x;
        if (gtid == 0) g_is64 = is64 ? 1 : 0;
        if (is64) {
            const long long* ei = (const long long*)eiv;
            for (int e = gtid; e < EE; e += CSTRIDE)
                atomicAdd(&g_cnt[(int)ei[EE + e]], 1);
        } else {
            for (int e = gtid; e < EE; e += CSTRIDE)
                atomicAdd(&g_cnt[ei32[EE + e]], 1);
        }
    }

    __shared__ float xsT[32][129];
    __shared__ float ws[32 * 64];
    int t = threadIdx.x;
    int half = t >> 7;
    int nl = t & 127;
    int node0 = blockIdx.x * 128;

    float acc[32];
#pragma unroll
    for (int c = 0; c < 32; c++) acc[c] = 0.f;

    for (int kt = 0; kt < INC; kt += 32) {
        for (int i = t; i < 32 * 64; i += 256)
            ws[i] = w1[(kt + (i >> 6)) * 64 + (i & 63)];
        for (int i = t; i < 1024; i += 256) {
            int r = i >> 3, c4 = i & 7;
            int node = node0 + r;
            float4 v = make_float4(0.f, 0.f, 0.f, 0.f);
            if (node < NN)
                v = *(const float4*)&x[(size_t)node * INC + kt + c4 * 4];
            xsT[c4 * 4 + 0][r] = v.x;
            xsT[c4 * 4 + 1][r] = v.y;
            xsT[c4 * 4 + 2][r] = v.z;
            xsT[c4 * 4 + 3][r] = v.w;
        }
        __syncthreads();
#pragma unroll 4
        for (int k = 0; k < 32; k++) {
            float xv = xsT[k][nl];
            const float4* wr = (const float4*)&ws[k * 64 + half * 32];
#pragma unroll
            for (int c4 = 0; c4 < 8; c4++) {
                float4 w4 = wr[c4];
                acc[c4 * 4 + 0] += xv * w4.x;
                acc[c4 * 4 + 1] += xv * w4.y;
                acc[c4 * 4 + 2] += xv * w4.z;
                acc[c4 * 4 + 3] += xv * w4.w;
            }
        }
        __syncthreads();
    }
    int node = node0 + nl;
    if (node < NN) {
        float* px = &g_x0[node * 64 + half * 32];
        float* ph = &g_hbuf[0][node * 64 + half * 32];
#pragma unroll
        for (int c4 = 0; c4 < 8; c4++) {
            float4 v;
            v.x = fmaxf(acc[c4 * 4 + 0] + b1[half * 32 + c4 * 4 + 0], 0.f);
            v.y = fmaxf(acc[c4 * 4 + 1] + b1[half * 32 + c4 * 4 + 1], 0.f);
            v.z = fmaxf(acc[c4 * 4 + 2] + b1[half * 32 + c4 * 4 + 2], 0.f);
            v.w = fmaxf(acc[c4 * 4 + 3] + b1[half * 32 + c4 * 4 + 3], 0.f);
            *(float4*)&px[c4 * 4] = v;
            *(float4*)&ph[c4 * 4] = v;
        }
    }
}

// ---------------- launch 1: single-pass lookback scan (replay-safe) ----------------
__global__ __launch_bounds__(1024) void k_scan() {
    __shared__ int wsum[32];
    __shared__ int pred[64];
    int par = g_par;
    int t = threadIdx.x, b = blockIdx.x;
    int i = b * 1024 + t;
    int v = (i < NN) ? g_cnt[i] : 0;
    int lane = t & 31, wid = t >> 5;
    int s = v;
#pragma unroll
    for (int o = 1; o < 32; o <<= 1) {
        int u = __shfl_up_sync(0xffffffffu, s, o);
        if (lane >= o) s += u;
    }
    if (lane == 31) wsum[wid] = s;
    __syncthreads();
    if (wid == 0) {
        int ws = wsum[lane];
#pragma unroll
        for (int o = 1; o < 32; o <<= 1) {
            int u = __shfl_up_sync(0xffffffffu, ws, o);
            if (lane >= o) ws += u;
        }
        wsum[lane] = ws;
    }
    __syncthreads();
    int excl = s - v + (wid > 0 ? wsum[wid - 1] : 0);
    if (t == 1023)
        atomicExch(&g_bsumbuf[par][b], (excl + v) | (1 << 30));
    if (t < 64) {
        int pv = 0;
        if (t < b) {
            while ((pv = atomicAdd(&g_bsumbuf[par][t], 0)) == 0) {}
            pv &= ~(1 << 30);
        }
        pred[t] = pv;
    }
    __syncthreads();
    for (int o = 32; o > 0; o >>= 1) {
        if (t < o) pred[t] += pred[t + o];
        __syncthreads();
    }
    int off = pred[0];
    if (i < NN) {
        g_rowptr[i] = excl + off;
        g_dinv[i] = rsqrtf((float)(v + 1));
        g_fill[i] = 0;
        g_cnt[i] = 0;
    }
    if (i == NN - 1) g_rowptr[NN] = EE;
    __syncthreads();
    __threadfence();
    if (t == 0) {
        int d = atomicAdd(&g_done, 1);
        if (d == NBLK - 1) {
            for (int j = 0; j < NBLK; j++) g_bsumbuf[par][j] = 0;
            g_done = 0;
            __threadfence();
            g_par = par ^ 1;
        }
    }
}

// ---------------- launch 2: fill CSR ----------------
__global__ void k_fill(const void* eiv) {
    int e = blockIdx.x * blockDim.x + threadIdx.x;
    if (e >= EE) return;
    int s, d;
    if (g_is64) {
        const long long* ei = (const long long*)eiv;
        s = (int)ei[e];
        d = (int)ei[EE + e];
    } else {
        const int* ei = (const int*)eiv;
        s = ei[e];
        d = ei[EE + e];
    }
    int pos = g_rowptr[d] + atomicAdd(&g_fill[d], 1);
    g_edge[pos] = make_int2(s, __float_as_int(g_dinv[s] * g_dinv[d]));
}

// ---------------- launch 3+: fused GCNII layer ----------------
// warp = 4 nodes. Per node: float4/half-warp gather, z staged straight to
// smem (STS.128, conflict-free) -> low regs -> 5 blocks/SM. GEMM reads z
// back as broadcast LDS.128 per k-quad.
__global__ __launch_bounds__(256, 5) void k_layer(const float* __restrict__ W,
                                                  float beta, int p) {
    __shared__ float ws[64 * 64];
    __shared__ float zrow[8][4][64];    // [warp][node][k]
    int t = threadIdx.x, w = t >> 5, lane = t & 31;
    int l2 = lane * 2;
    int hl = lane >> 4;          // edge parity within pair
    int fl = lane & 15;          // feature quad id
    for (int i = t; i < 4096; i += 256) ws[i] = W[i];
    __syncthreads();

    const float4* __restrict__ hin4 = (const float4*)g_hbuf[p];
    const float4* __restrict__ x04 = (const float4*)g_x0;
    float* __restrict__ hout = g_hbuf[p ^ 1];
    int warpG = blockIdx.x * 8 + w;
    int nW = gridDim.x * 8;
    float ob = 1.f - beta;

    for (int base = warpG * 4; base < NN; base += nW * 4) {
#pragma unroll
        for (int q = 0; q < 4; q++) {
            int node = base + q;
            if (node >= NN) {
                if (hl == 0) *(float4*)&zrow[w][q][fl * 4] = make_float4(0.f, 0.f, 0.f, 0.f);
                continue;
            }
            float4 acc = make_float4(0.f, 0.f, 0.f, 0.f);
            int e0 = g_rowptr[node], e1 = g_rowptr[node + 1];
            for (int eb = e0; eb < e1; eb += 32) {
                int ee = eb + lane;
                int2 E = (ee < e1) ? g_edge[ee] : make_int2(0, 0);
                int cc = E.x;
                float vv = __int_as_float(E.y);
                int cn = min(32, e1 - eb);
                for (int j = 0; j < cn; j += 8) {
                    int sA = __shfl_sync(0xffffffffu, cc, j + hl);
                    int sB = __shfl_sync(0xffffffffu, cc, j + 2 + hl);
                    int sC = __shfl_sync(0xffffffffu, cc, j + 4 + hl);
                    int sD = __shfl_sync(0xffffffffu, cc, j + 6 + hl);
                    float vA = __shfl_sync(0xffffffffu, vv, j + hl);
                    float vB = __shfl_sync(0xffffffffu, vv, j + 2 + hl);
                    float vC = __shfl_sync(0xffffffffu, vv, j + 4 + hl);
                    float vD = __shfl_sync(0xffffffffu, vv, j + 6 + hl);
                    float4 hA = hin4[sA * 16 + fl];
                    float4 hB = hin4[sB * 16 + fl];
                    float4 hC = hin4[sC * 16 + fl];
                    float4 hD = hin4[sD * 16 + fl];
                    acc.x += vA * hA.x; acc.y += vA * hA.y;
                    acc.z += vA * hA.z; acc.w += vA * hA.w;
                    acc.x += vB * hB.x; acc.y += vB * hB.y;
                    acc.z += vB * hB.z; acc.w += vB * hB.w;
                    acc.x += vC * hC.x; acc.y += vC * hC.y;
                    acc.z += vC * hC.z; acc.w += vC * hC.w;
                    acc.x += vD * hD.x; acc.y += vD * hD.y;
                    acc.z += vD * hD.z; acc.w += vD * hD.w;
                }
            }
            acc.x += __shfl_xor_sync(0xffffffffu, acc.x, 16);
            acc.y += __shfl_xor_sync(0xffffffffu, acc.y, 16);
            acc.z += __shfl_xor_sync(0xffffffffu, acc.z, 16);
            acc.w += __shfl_xor_sync(0xffffffffu, acc.w, 16);
            if (hl == 0) {
                float di = g_dinv[node];
                float dd = di * di;
                float4 hme = hin4[node * 16 + fl];
                float4 xm = x04[node * 16 + fl];
                float4 z;
                z.x = 0.5f * (acc.x + dd * hme.x) + 0.5f * xm.x;
                z.y = 0.5f * (acc.y + dd * hme.y) + 0.5f * xm.y;
                z.z = 0.5f * (acc.z + dd * hme.z) + 0.5f * xm.z;
                z.w = 0.5f * (acc.w + dd * hme.w) + 0.5f * xm.w;
                *(float4*)&zrow[w][q][fl * 4] = z;   // STS.128, conflict-free
            }
        }
        __syncwarp();

        // GEMM: per k-quad, 4 broadcast LDS.128 (one per node) + 4 LDS.64 (W)
        float2 sA = make_float2(0.f, 0.f), sB = make_float2(0.f, 0.f);
        float2 sC = make_float2(0.f, 0.f), sD = make_float2(0.f, 0.f);
#pragma unroll
        for (int k4 = 0; k4 < 16; k4++) {
            float4 zA = *(const float4*)&zrow[w][0][k4 * 4];
            float4 zB = *(const float4*)&zrow[w][1][k4 * 4];
            float4 zC = *(const float4*)&zrow[w][2][k4 * 4];
            float4 zD = *(const float4*)&zrow[w][3][k4 * 4];
#pragma unroll
            for (int j = 0; j < 4; j++) {
                float2 wk = *(const float2*)&ws[(k4 * 4 + j) * 64 + l2];
                float za = (j == 0) ? zA.x : (j == 1) ? zA.y : (j == 2) ? zA.z : zA.w;
                float zb = (j == 0) ? zB.x : (j == 1) ? zB.y : (j == 2) ? zB.z : zB.w;
                float zc = (j == 0) ? zC.x : (j == 1) ? zC.y : (j == 2) ? zC.z : zC.w;
                float zd = (j == 0) ? zD.x : (j == 1) ? zD.y : (j == 2) ? zD.z : zD.w;
                sA.x += za * wk.x; sA.y += za * wk.y;
                sB.x += zb * wk.x; sB.y += zb * wk.y;
                sC.x += zc * wk.x; sC.y += zc * wk.y;
                sD.x += zd * wk.x; sD.y += zd * wk.y;
            }
        }
#pragma unroll
        for (int q = 0; q < 4; q++) {
            int node = base + q;
            if (node < NN) {
                float2 zc2 = *(const float2*)&zrow[w][q][l2];
                float2 sq = (q == 0) ? sA : (q == 1) ? sB : (q == 2) ? sC : sD;
                float o0 = fmaxf(ob * zc2.x + beta * sq.x, 0.f);
                float o1 = fmaxf(ob * zc2.y + beta * sq.y, 0.f);
                *(float2*)&hout[node * 64 + l2] = make_float2(o0, o1);
            }
        }
        __syncwarp();
    }
}

// ---------------- output: lin2 + log_softmax ----------------
__global__ __launch_bounds__(256) void k_out(const float* __restrict__ w2,
                                             const float* __restrict__ b2,
                                             float* __restrict__ out) {
    __shared__ float ws[64 * OC];
    __shared__ float bs[OC];
    __shared__ float zsm[8][64];
    int t = threadIdx.x, w = t >> 5, lane = t & 31;
    for (int i = t; i < 64 * OC; i += 256) ws[i] = w2[i];
    if (t < OC) bs[t] = b2[t];
    __syncthreads();

    const float* h = g_hbuf[0];  // NL even -> final state in buffer 0
    int warpG = blockIdx.x * 8 + w;
    int nW = gridDim.x * 8;

    for (int node = warpG; node < NN; node += nW) {
        float2 h2 = *(const float2*)&h[node * 64 + lane * 2];
        *(float2*)&zsm[w][lane * 2] = h2;
        __syncwarp();
        int c0 = lane;
        int c1 = lane + 32;
        float v0 = bs[c0];
        float v1 = (lane < 8) ? bs[c1] : 0.f;
#pragma unroll
        for (int k = 0; k < 64; k++) {
            float zk = zsm[w][k];
            v0 += zk * ws[k * OC + c0];
            if (lane < 8) v1 += zk * ws[k * OC + c1];
        }
        float m = v0;
        if (lane < 8) m = fmaxf(m, v1);
#pragma unroll
        for (int o = 16; o > 0; o >>= 1)
            m = fmaxf(m, __shfl_xor_sync(0xffffffffu, m, o));
        float se = expf(v0 - m) + ((lane < 8) ? expf(v1 - m) : 0.f);
#pragma unroll
        for (int o = 16; o > 0; o >>= 1)
            se += __shfl_xor_sync(0xffffffffu, se, o);
        float lse = m + logf(se);
        out[node * OC + c0] = v0 - lse;
        if (lane < 8) out[node * OC + c1] = v1 - lse;
        __syncwarp();
    }
}

// ---------------- launch ----------------
extern "C" void kernel_launch(void* const* d_in, const int* in_sizes, int n_in,
                              void* d_out, int out_size) {
    (void)in_sizes; (void)n_in; (void)out_size;
    const float* x  = (const float*)d_in[0];
    const void*  ei = d_in[1];
    const float* w1 = (const float*)d_in[2];
    const float* b1 = (const float*)d_in[3];
    const float* cw = (const float*)d_in[4];
    const float* w2 = (const float*)d_in[5];
    const float* b2 = (const float*)d_in[6];
    float* out = (float*)d_out;

    k_lin1<<<391, 256>>>(x, w1, b1, ei);        // #0
    k_scan<<<NBLK, 1024>>>();                    // #1
    k_fill<<<(EE + 255) / 256, 256>>>(ei);       // #2
    for (int l = 0; l < NL; l++) {               // #3 = layer 0 (profiled)
        float beta = logf(1.0f / (float)(l + 1) + 1.0f);
        k_layer<<<148 * 8, 256>>>(cw + (size_t)l * HH * HH, beta, l & 1);
    }
    k_out<<<512, 256>>>(w2, b2, out);
}